// round 10
// baseline (speedup 1.0000x reference)
#include <cuda_runtime.h>
#include <cuda_bf16.h>
#include <cstdint>

#define F 256
#define NTOK 1024
#define NB 16
#define ROWS (NB*NTOK)   // 16384

// ---------------- scratch ----------------------------------------------------
__device__ __nv_bfloat16 g_xb[ROWS*F];
__device__ __nv_bfloat16 g_alpha[ROWS*F];
__device__ __nv_bfloat16 g_beta[ROWS*F];
__device__ __nv_bfloat16 g_up[ROWS*F];
__device__ __nv_bfloat16 g_Mp[NB*F*F];       // M'_T[b][g][k]  (K-major)
__device__ __nv_bfloat16 g_Wbf[3*F*F];
__device__ float g_Wur[F*F];
__device__ float g_bp[F];
__device__ float g_d[ROWS];

// ---------------- helpers ----------------------------------------------------
__device__ __forceinline__ uint32_t cvta_s(const void* p) {
    return (uint32_t)__cvta_generic_to_shared(p);
}
__device__ __forceinline__ void cp16(void* s, const void* g) {
    asm volatile("cp.async.cg.shared.global [%0], [%1], 16;\n"
        :: "r"(cvta_s(s)), "l"(g));
}
__device__ __forceinline__ void cp_commit() { asm volatile("cp.async.commit_group;\n"); }
__device__ __forceinline__ void cp_wait1()  { asm volatile("cp.async.wait_group 1;\n"); }
__device__ __forceinline__ void cp_wait0()  { asm volatile("cp.async.wait_group 0;\n"); }

__device__ __forceinline__ void ldmx4(uint32_t r[4], uint32_t addr) {
    asm volatile("ldmatrix.sync.aligned.m8n8.x4.shared.b16 {%0,%1,%2,%3}, [%4];\n"
        : "=r"(r[0]), "=r"(r[1]), "=r"(r[2]), "=r"(r[3]) : "r"(addr));
}
__device__ __forceinline__ void ldmx4t(uint32_t r[4], uint32_t addr) {
    asm volatile("ldmatrix.sync.aligned.m8n8.x4.trans.shared.b16 {%0,%1,%2,%3}, [%4];\n"
        : "=r"(r[0]), "=r"(r[1]), "=r"(r[2]), "=r"(r[3]) : "r"(addr));
}
__device__ __forceinline__ void mma_bf16(float c[4], const uint32_t a[4], const uint32_t b[2]) {
    asm volatile(
        "mma.sync.aligned.m16n8k16.row.col.f32.bf16.bf16.f32 "
        "{%0,%1,%2,%3}, {%4,%5,%6,%7}, {%8,%9}, {%0,%1,%2,%3};\n"
        : "+f"(c[0]), "+f"(c[1]), "+f"(c[2]), "+f"(c[3])
        : "r"(a[0]), "r"(a[1]), "r"(a[2]), "r"(a[3]), "r"(b[0]), "r"(b[1]));
}

// ---------------- K0: combined weight ---------------------------------------
__global__ void k0_combine(const float* __restrict__ Wr,
                           const float* __restrict__ Wu,
                           const float* __restrict__ bu) {
    __shared__ float sWr[F];
    int g = blockIdx.x;
    int f = threadIdx.x;
    sWr[f] = Wr[g*F + f];
    __syncthreads();
    float acc = 0.f;
    #pragma unroll 8
    for (int h = 0; h < F; ++h) acc = fmaf(sWr[h], Wu[h*F + f], acc);
    g_Wur[g*F + f] = acc;
    if (f == 0) {
        float bb = 0.f;
        for (int h = 0; h < F; ++h) bb = fmaf(sWr[h], bu[h], bb);
        g_bp[g] = bb;
    }
}

// ---------------- conversions ------------------------------------------------
__global__ void kconv_x(const float* __restrict__ x) {
    int i = blockIdx.x * blockDim.x + threadIdx.x;
    float4 v = ((const float4*)x)[i];
    ((__nv_bfloat162*)g_xb)[2*i]   = __floats2bfloat162_rn(v.x, v.y);
    ((__nv_bfloat162*)g_xb)[2*i+1] = __floats2bfloat162_rn(v.z, v.w);
}
__global__ void kconv_w(const float* __restrict__ Wa, const float* __restrict__ Wb) {
    int i = blockIdx.x * blockDim.x + threadIdx.x;
    const float* src = (i < 16384) ? Wa : (i < 32768) ? Wb : (const float*)g_Wur;
    int j = i & 16383;
    float4 v = ((const float4*)src)[j];
    ((__nv_bfloat162*)g_Wbf)[2*i]   = __floats2bfloat162_rn(v.x, v.y);
    ((__nv_bfloat162*)g_Wbf)[2*i+1] = __floats2bfloat162_rn(v.z, v.w);
}

// ============================================================================
// GEMM core: CTA 256(m) x 128(n), BK=64, 8 warps (4m x 2n), warp tile 64x64.
// LDSM bytes/MAC cut 33% vs 32x64. 1 CTA/SM. Smem double-buffered (108 KB).
// Leaves result in acc[4][8][4].
// ============================================================================
#define LDSTRIDE 72

#define GEMM_CORE(aG, bG, NK) \
    __nv_bfloat16* As = (__nv_bfloat16*)smem_raw;            /* 2 x 256 x 72 */ \
    __nv_bfloat16* Bs = As + 2*256*LDSTRIDE;                 /* 2 x 128 x 72 */ \
    const int tid = threadIdx.x, lane = tid & 31, wid = tid >> 5; \
    const int wm = wid >> 1, wn = wid & 1; \
    float acc[4][8][4]; \
    _Pragma("unroll") \
    for (int i = 0; i < 4; ++i) \
        _Pragma("unroll") \
        for (int j = 0; j < 8; ++j) \
            _Pragma("unroll") \
            for (int e = 0; e < 4; ++e) acc[i][j][e] = 0.f; \
    { \
        int r = tid >> 3, c8 = (tid & 7)*8; \
        _Pragma("unroll") \
        for (int l = 0; l < 8; ++l) \
            cp16(&As[(0*256 + r + l*32)*LDSTRIDE + c8], &(aG)[(r + l*32)*F + c8]); \
        _Pragma("unroll") \
        for (int l = 0; l < 4; ++l) \
            cp16(&Bs[(0*128 + r + l*32)*LDSTRIDE + c8], &(bG)[(r + l*32)*F + c8]); \
        cp_commit(); \
    } \
    const int NIT = (NK)/64; \
    for (int it = 0; it < NIT; ++it) { \
        if (it + 1 < NIT) { \
            int kt = (it+1)*64, buf = (it+1)&1; \
            int r = tid >> 3, c8 = (tid & 7)*8; \
            _Pragma("unroll") \
            for (int l = 0; l < 8; ++l) \
                cp16(&As[(buf*256 + r + l*32)*LDSTRIDE + c8], &(aG)[(r + l*32)*F + kt + c8]); \
            _Pragma("unroll") \
            for (int l = 0; l < 4; ++l) \
                cp16(&Bs[(buf*128 + r + l*32)*LDSTRIDE + c8], &(bG)[(r + l*32)*F + kt + c8]); \
            cp_commit(); cp_wait1(); \
        } else cp_wait0(); \
        __syncthreads(); \
        const int buf = it & 1; \
        _Pragma("unroll") \
        for (int ks = 0; ks < 4; ++ks) { \
            const int k0 = ks * 16; \
            uint32_t afr[4][4]; \
            _Pragma("unroll") \
            for (int mt = 0; mt < 4; ++mt) \
                ldmx4(afr[mt], cvta_s(&As[(buf*256 + wm*64 + mt*16 + (lane & 15))*LDSTRIDE \
                                          + k0 + (lane >> 4)*8])); \
            uint32_t bfr[8][2]; \
            _Pragma("unroll") \
            for (int bt = 0; bt < 4; ++bt) { \
                uint32_t t[4]; \
                int n  = wn*64 + bt*16 + (lane & 7) + ((lane >> 4) & 1)*8; \
                int kk = k0 + ((lane >> 3) & 1)*8; \
                ldmx4(t, cvta_s(&Bs[(buf*128 + n)*LDSTRIDE + kk])); \
                bfr[bt*2][0] = t[0]; bfr[bt*2][1] = t[1]; \
                bfr[bt*2+1][0] = t[2]; bfr[bt*2+1][1] = t[3]; \
            } \
            _Pragma("unroll") \
            for (int mt = 0; mt < 4; ++mt) \
                _Pragma("unroll") \
                for (int nt = 0; nt < 8; ++nt) \
                    mma_bf16(acc[mt][nt], afr[mt], bfr[nt]); \
        } \
        __syncthreads(); \
    }

#define GEMM_SMEM ((2*256*LDSTRIDE + 2*128*LDSTRIDE)*2)   // 110592 B

// ---------------- G1: projections --------------------------------------------
__global__ __launch_bounds__(256, 1) void g1_proj() {
    extern __shared__ char smem_raw[];
    const int z = blockIdx.z;
    const int row0 = blockIdx.x * 256;
    const int col0 = blockIdx.y * 128;
    const __nv_bfloat16* __restrict__ W = g_Wbf + z*F*F;
    __nv_bfloat16* __restrict__ out = (z == 0) ? g_alpha : (z == 1) ? g_beta : g_up;
    const __nv_bfloat16* aG = g_xb + row0*F;
    const __nv_bfloat16* bG = W + col0*F;

    GEMM_CORE(aG, bG, F)

    const int rc = lane >> 2, cc = (lane & 3)*2;
    #pragma unroll
    for (int mt = 0; mt < 4; ++mt) {
        int rb = row0 + wm*64 + mt*16 + rc;
        #pragma unroll
        for (int nt = 0; nt < 8; ++nt) {
            int col = col0 + wn*64 + nt*8 + cc;
            #pragma unroll
            for (int h = 0; h < 2; ++h) {
                int row = rb + h*8;
                float v0 = acc[mt][nt][2*h], v1 = acc[mt][nt][2*h+1];
                if (z == 2) { v0 += g_bp[col]; v1 += g_bp[col+1]; }
                *(__nv_bfloat162*)&out[row*F + col] = __floats2bfloat162_rn(v0, v1);
            }
        }
    }
}

// ---------------- kdiag ------------------------------------------------------
__global__ void kdiag() {
    int gw = (blockIdx.x * blockDim.x + threadIdx.x) >> 5;
    int lane = threadIdx.x & 31;
    const __nv_bfloat162* a = (const __nv_bfloat162*)(g_alpha + gw*F);
    const __nv_bfloat162* b = (const __nv_bfloat162*)(g_beta  + gw*F);
    float s = 0.f;
    #pragma unroll
    for (int t = lane; t < 128; t += 32) {
        float2 av = __bfloat1622float2(a[t]);
        float2 bv = __bfloat1622float2(b[t]);
        s = fmaf(av.x, bv.x, s);
        s = fmaf(av.y, bv.y, s);
    }
    #pragma unroll
    for (int o = 16; o > 0; o >>= 1) s += __shfl_xor_sync(0xffffffffu, s, o);
    if (lane == 0) g_d[gw] = s;
}

// ---------------- G2: M'_T[g][k] = sum_n up[n,g]*beta[n,k] -------------------
// 64x64 tiles, grid (4,4,16) = 256 CTAs, 128 threads, warp tile 32x32, BK=32.
__global__ __launch_bounds__(128) void g2_mprime() {
    const int b  = blockIdx.z;
    const int m0 = blockIdx.x * 64;        // g
    const int n0 = blockIdx.y * 64;        // k
    const __nv_bfloat16* __restrict__ Aop = g_up   + b*NTOK*F;
    const __nv_bfloat16* __restrict__ Bop = g_beta + b*NTOK*F;

    __shared__ __nv_bfloat16 Ut[2][32][72];
    __shared__ __nv_bfloat16 Bt[2][32][72];

    const int tid = threadIdx.x, lane = tid & 31, wid = tid >> 5;
    const int wm = wid & 1, wn = wid >> 1;

    float acc[2][4][4];
    #pragma unroll
    for (int i = 0; i < 2; ++i)
        #pragma unroll
        for (int j = 0; j < 4; ++j)
            #pragma unroll
            for (int e = 0; e < 4; ++e) acc[i][j][e] = 0.f;

#define G2_LOAD(buf, rt) { \
    _Pragma("unroll") \
    for (int l = 0; l < 2; ++l) { \
        int id = tid + l*128; \
        int r = id >> 3, c8 = (id & 7)*8; \
        cp16(&Ut[buf][r][c8], &Aop[((rt) + r)*F + m0 + c8]); \
        cp16(&Bt[buf][r][c8], &Bop[((rt) + r)*F + n0 + c8]); \
    } cp_commit(); }

    G2_LOAD(0, 0)
    const int NIT = NTOK/32;
    for (int it = 0; it < NIT; ++it) {
        if (it + 1 < NIT) { G2_LOAD((it+1)&1, (it+1)*32) cp_wait1(); }
        else cp_wait0();
        __syncthreads();
        const int buf = it & 1;
        #pragma unroll
        for (int ks = 0; ks < 2; ++ks) {
            const int r0 = ks * 16;
            uint32_t a[2][4];
            #pragma unroll
            for (int mt = 0; mt < 2; ++mt) {
                int rr = r0 + (lane & 7) + ((lane >> 4) & 1)*8;
                int cm = wm*32 + mt*16 + ((lane >> 3) & 1)*8;
                ldmx4t(a[mt], cvta_s(&Ut[buf][rr][cm]));
            }
            uint32_t bfr[4][2];
            {
                uint32_t t[4];
                int rr = r0 + (lane & 7) + ((lane >> 3) & 1)*8;
                #pragma unroll
                for (int bt = 0; bt < 2; ++bt) {
                    int cn = wn*32 + bt*16 + ((lane >> 4) & 1)*8;
                    ldmx4t(t, cvta_s(&Bt[buf][rr][cn]));
                    bfr[bt*2][0] = t[0]; bfr[bt*2][1] = t[1];
                    bfr[bt*2+1][0] = t[2]; bfr[bt*2+1][1] = t[3];
                }
            }
            #pragma unroll
            for (int mt = 0; mt < 2; ++mt)
                #pragma unroll
                for (int nt = 0; nt < 4; ++nt)
                    mma_bf16(acc[mt][nt], a[mt], bfr[nt]);
        }
        __syncthreads();
    }
#undef G2_LOAD

    const int rc = lane >> 2, cc = (lane & 3)*2;
    __nv_bfloat16* __restrict__ Mp = g_Mp + b*F*F;
    #pragma unroll
    for (int mt = 0; mt < 2; ++mt) {
        int rb = m0 + wm*32 + mt*16 + rc;
        #pragma unroll
        for (int nt = 0; nt < 4; ++nt) {
            int col = n0 + wn*32 + nt*8 + cc;
            #pragma unroll
            for (int h = 0; h < 2; ++h) {
                int row = rb + h*8;
                *(__nv_bfloat162*)&Mp[row*F + col] =
                    __floats2bfloat162_rn(acc[mt][nt][2*h], acc[mt][nt][2*h+1]);
            }
        }
    }
}

// ---------------- G3: out = (alpha @ M'_T^T - d*up)/N + x --------------------
__global__ __launch_bounds__(256, 1) void g3_out(const float* __restrict__ x,
                                                 float* __restrict__ out) {
    extern __shared__ char smem_raw[];
    const int row0 = blockIdx.x * 256;
    const int col0 = blockIdx.y * 128;
    const int b = row0 >> 10;
    const __nv_bfloat16* __restrict__ Mp = g_Mp + b*F*F;   // [g][k] K-major
    const __nv_bfloat16* aG = g_alpha + row0*F;
    const __nv_bfloat16* bG = Mp + col0*F;

    GEMM_CORE(aG, bG, F)

    const float inv = 1.0f / (float)NTOK;
    const int rc = lane >> 2, cc = (lane & 3)*2;
    #pragma unroll
    for (int mt = 0; mt < 4; ++mt) {
        int rb = row0 + wm*64 + mt*16 + rc;
        #pragma unroll
        for (int h = 0; h < 2; ++h) {
            int row = rb + h*8;
            float di = g_d[row];
            #pragma unroll
            for (int nt = 0; nt < 8; ++nt) {
                int col = col0 + wn*64 + nt*8 + cc;
                float2 uv = __bfloat1622float2(*(const __nv_bfloat162*)&g_up[row*F + col]);
                float2 xv = *(const float2*)&x[row*F + col];
                float2 o;
                o.x = (acc[mt][nt][2*h]   - di*uv.x) * inv + xv.x;
                o.y = (acc[mt][nt][2*h+1] - di*uv.y) * inv + xv.y;
                *(float2*)&out[row*F + col] = o;
            }
        }
    }
}

// ---------------------------------------------------------------------------
extern "C" void kernel_launch(void* const* d_in, const int* in_sizes, int n_in,
                              void* d_out, int out_size) {
    const float* x  = (const float*)d_in[0];
    const float* Wa = (const float*)d_in[1];
    const float* Wb = (const float*)d_in[2];
    const float* Wu = (const float*)d_in[3];
    const float* bu = (const float*)d_in[4];
    const float* Wr = (const float*)d_in[5];
    float* out = (float*)d_out;

    static int inited = 0;
    static cudaStream_t s2;
    static cudaEvent_t eA, eB, eC, eD;
    if (!inited) {
        cudaFuncSetAttribute(g1_proj, cudaFuncAttributeMaxDynamicSharedMemorySize, GEMM_SMEM);
        cudaFuncSetAttribute(g3_out, cudaFuncAttributeMaxDynamicSharedMemorySize, GEMM_SMEM);
        cudaStreamCreateWithFlags(&s2, cudaStreamNonBlocking);
        cudaEventCreateWithFlags(&eA, cudaEventDisableTiming);
        cudaEventCreateWithFlags(&eB, cudaEventDisableTiming);
        cudaEventCreateWithFlags(&eC, cudaEventDisableTiming);
        cudaEventCreateWithFlags(&eD, cudaEventDisableTiming);
        inited = 1;
    }

    // fork: kconv_x on s2 || (k0 -> kconv_w) on main
    cudaEventRecord(eA, 0);
    cudaStreamWaitEvent(s2, eA, 0);
    kconv_x<<<ROWS*F/4/256, 256, 0, s2>>>(x);
    k0_combine<<<F, F>>>(Wr, Wu, bu);
    kconv_w<<<3*F*F/4/256, 256>>>(Wa, Wb);
    cudaEventRecord(eB, s2);
    cudaStreamWaitEvent(0, eB, 0);

    g1_proj<<<dim3(ROWS/256, F/128, 3), 256, GEMM_SMEM>>>();

    // fork: kdiag on s2 || g2 on main
    cudaEventRecord(eC, 0);
    cudaStreamWaitEvent(s2, eC, 0);
    kdiag<<<ROWS*32/256, 256, 0, s2>>>();
    g2_mprime<<<dim3(F/64, F/64, NB), 128>>>();
    cudaEventRecord(eD, s2);
    cudaStreamWaitEvent(0, eD, 0);

    g3_out<<<dim3(ROWS/256, F/128), 256, GEMM_SMEM>>>(x, out);
}

// round 11
// speedup vs baseline: 1.0599x; 1.0599x over previous
#include <cuda_runtime.h>
#include <cuda_bf16.h>
#include <cstdint>

#define F 256
#define NTOK 1024
#define NB 16
#define ROWS (NB*NTOK)   // 16384

// ---------------- scratch ----------------------------------------------------
__device__ __nv_bfloat16 g_xb[ROWS*F];
__device__ __nv_bfloat16 g_alpha[ROWS*F];
__device__ __nv_bfloat16 g_beta[ROWS*F];
__device__ __nv_bfloat16 g_up[ROWS*F];
__device__ __nv_bfloat16 g_Mp[NB*F*F];       // M'_T[b][g][k]  (K-major)
__device__ __nv_bfloat16 g_Wbf[3*F*F];
__device__ float g_bp[F];
__device__ float g_d[ROWS];

// ---------------- helpers ----------------------------------------------------
__device__ __forceinline__ uint32_t cvta_s(const void* p) {
    return (uint32_t)__cvta_generic_to_shared(p);
}
__device__ __forceinline__ void cp16(void* s, const void* g) {
    asm volatile("cp.async.cg.shared.global [%0], [%1], 16;\n"
        :: "r"(cvta_s(s)), "l"(g));
}
__device__ __forceinline__ void cp_commit() { asm volatile("cp.async.commit_group;\n"); }
__device__ __forceinline__ void cp_wait1()  { asm volatile("cp.async.wait_group 1;\n"); }
__device__ __forceinline__ void cp_wait0()  { asm volatile("cp.async.wait_group 0;\n"); }

__device__ __forceinline__ void ldmx4(uint32_t r[4], uint32_t addr) {
    asm volatile("ldmatrix.sync.aligned.m8n8.x4.shared.b16 {%0,%1,%2,%3}, [%4];\n"
        : "=r"(r[0]), "=r"(r[1]), "=r"(r[2]), "=r"(r[3]) : "r"(addr));
}
__device__ __forceinline__ void ldmx4t(uint32_t r[4], uint32_t addr) {
    asm volatile("ldmatrix.sync.aligned.m8n8.x4.trans.shared.b16 {%0,%1,%2,%3}, [%4];\n"
        : "=r"(r[0]), "=r"(r[1]), "=r"(r[2]), "=r"(r[3]) : "r"(addr));
}
__device__ __forceinline__ void mma_bf16(float c[4], const uint32_t a[4], const uint32_t b[2]) {
    asm volatile(
        "mma.sync.aligned.m16n8k16.row.col.f32.bf16.bf16.f32 "
        "{%0,%1,%2,%3}, {%4,%5,%6,%7}, {%8,%9}, {%0,%1,%2,%3};\n"
        : "+f"(c[0]), "+f"(c[1]), "+f"(c[2]), "+f"(c[3])
        : "r"(a[0]), "r"(a[1]), "r"(a[2]), "r"(a[3]), "r"(b[0]), "r"(b[1]));
}

// ---------------- KPREP_W: combined weight + all weight conversions ----------
// block g (256 blocks x 256 threads):
//   Wur[g][f] = sum_h Wr[g][h]*Wu[h][f]  -> bf16 into g_Wbf[2]
//   b'[g]     = sum_h Wr[g][h]*bu[h]
//   convert Wa[g][:], Wb[g][:] rows -> g_Wbf[0], g_Wbf[1]
__global__ void kprep_w(const float* __restrict__ Wr,
                        const float* __restrict__ Wu,
                        const float* __restrict__ bu,
                        const float* __restrict__ Wa,
                        const float* __restrict__ Wb) {
    __shared__ float sWr[F];
    int g = blockIdx.x;
    int f = threadIdx.x;
    sWr[f] = Wr[g*F + f];
    __syncthreads();
    float acc = 0.f;
    #pragma unroll 8
    for (int h = 0; h < F; ++h) acc = fmaf(sWr[h], Wu[h*F + f], acc);
    g_Wbf[2*F*F + g*F + f] = __float2bfloat16(acc);
    g_Wbf[0*F*F + g*F + f] = __float2bfloat16(Wa[g*F + f]);
    g_Wbf[1*F*F + g*F + f] = __float2bfloat16(Wb[g*F + f]);
    if (f == 0) {
        float bb = 0.f;
        for (int h = 0; h < F; ++h) bb = fmaf(sWr[h], bu[h], bb);
        g_bp[g] = bb;
    }
}

// ---------------- kconv_x ----------------------------------------------------
__global__ void kconv_x(const float* __restrict__ x) {
    int i = blockIdx.x * blockDim.x + threadIdx.x;
    float4 v = ((const float4*)x)[i];
    ((__nv_bfloat162*)g_xb)[2*i]   = __floats2bfloat162_rn(v.x, v.y);
    ((__nv_bfloat162*)g_xb)[2*i+1] = __floats2bfloat162_rn(v.z, v.w);
}

// ============================================================================
// GEMM core (R6/R9-proven): CTA 128x128, BK=64, 8 warps (4m x 2n),
// warp tile 32x64. Smem + register-fragment double buffering.
// ============================================================================
#define LDSTRIDE 72

#define LOAD_FRAGS(dst_a, dst_b, buf, k0) { \
    _Pragma("unroll") \
    for (int mt = 0; mt < 2; ++mt) \
        ldmx4(dst_a[mt], cvta_s(&As[((buf)*128 + wm*32 + mt*16 + (lane & 15))*LDSTRIDE \
                                    + (k0) + (lane >> 4)*8])); \
    _Pragma("unroll") \
    for (int bt = 0; bt < 4; ++bt) { \
        uint32_t t[4]; \
        int n  = wn*64 + bt*16 + (lane & 7) + ((lane >> 4) & 1)*8; \
        int kk = (k0) + ((lane >> 3) & 1)*8; \
        ldmx4(t, cvta_s(&Bs[((buf)*128 + n)*LDSTRIDE + kk])); \
        dst_b[bt*2][0] = t[0]; dst_b[bt*2][1] = t[1]; \
        dst_b[bt*2+1][0] = t[2]; dst_b[bt*2+1][1] = t[3]; \
    } }

#define GEMM_CORE(aG, bG, NK) \
    __nv_bfloat16* As = (__nv_bfloat16*)smem_raw; \
    __nv_bfloat16* Bs = As + 2*128*LDSTRIDE; \
    const int tid = threadIdx.x, lane = tid & 31, wid = tid >> 5; \
    const int wm = wid & 3, wn = wid >> 2; \
    float acc[2][8][4]; \
    _Pragma("unroll") \
    for (int i = 0; i < 2; ++i) \
        _Pragma("unroll") \
        for (int j = 0; j < 8; ++j) \
            _Pragma("unroll") \
            for (int e = 0; e < 4; ++e) acc[i][j][e] = 0.f; \
    { \
        int r = tid >> 3, c8 = (tid & 7)*8; \
        _Pragma("unroll") \
        for (int l = 0; l < 4; ++l) { \
            cp16(&As[(0*128 + r + l*32)*LDSTRIDE + c8], &(aG)[(r + l*32)*F + c8]); \
            cp16(&Bs[(0*128 + r + l*32)*LDSTRIDE + c8], &(bG)[(r + l*32)*F + c8]); \
        } \
        cp_commit(); \
    } \
    const int NIT = (NK)/64; \
    for (int it = 0; it < NIT; ++it) { \
        if (it + 1 < NIT) { \
            int kt = (it+1)*64, buf = (it+1)&1; \
            int r = tid >> 3, c8 = (tid & 7)*8; \
            _Pragma("unroll") \
            for (int l = 0; l < 4; ++l) { \
                cp16(&As[(buf*128 + r + l*32)*LDSTRIDE + c8], &(aG)[(r + l*32)*F + kt + c8]); \
                cp16(&Bs[(buf*128 + r + l*32)*LDSTRIDE + c8], &(bG)[(r + l*32)*F + kt + c8]); \
            } \
            cp_commit(); cp_wait1(); \
        } else cp_wait0(); \
        __syncthreads(); \
        const int buf = it & 1; \
        uint32_t afr[2][2][4]; \
        uint32_t bfr[2][8][2]; \
        LOAD_FRAGS(afr[0], bfr[0], buf, 0) \
        _Pragma("unroll") \
        for (int ks = 0; ks < 4; ++ks) { \
            const int cur = ks & 1, nxt = cur ^ 1; \
            if (ks < 3) LOAD_FRAGS(afr[nxt], bfr[nxt], buf, (ks+1)*16) \
            _Pragma("unroll") \
            for (int mt = 0; mt < 2; ++mt) \
                _Pragma("unroll") \
                for (int nt = 0; nt < 8; ++nt) \
                    mma_bf16(acc[mt][nt], afr[cur][mt], bfr[cur][nt]); \
        } \
        __syncthreads(); \
    }

#define GEMM_SMEM (2*128*LDSTRIDE*2*2)   // 73728 B

// ---------------- G1: projections --------------------------------------------
__global__ __launch_bounds__(256, 2) void g1_proj() {
    extern __shared__ char smem_raw[];
    const int z = blockIdx.z;
    const int row0 = blockIdx.x * 128;
    const int col0 = blockIdx.y * 128;
    const __nv_bfloat16* __restrict__ W = g_Wbf + z*F*F;
    __nv_bfloat16* __restrict__ out = (z == 0) ? g_alpha : (z == 1) ? g_beta : g_up;
    const __nv_bfloat16* aG = g_xb + row0*F;
    const __nv_bfloat16* bG = W + col0*F;

    GEMM_CORE(aG, bG, F)

    const int rc = lane >> 2, cc = (lane & 3)*2;
    #pragma unroll
    for (int mt = 0; mt < 2; ++mt) {
        int rb = row0 + wm*32 + mt*16 + rc;
        #pragma unroll
        for (int nt = 0; nt < 8; ++nt) {
            int col = col0 + wn*64 + nt*8 + cc;
            #pragma unroll
            for (int h = 0; h < 2; ++h) {
                int row = rb + h*8;
                float v0 = acc[mt][nt][2*h], v1 = acc[mt][nt][2*h+1];
                if (z == 2) { v0 += g_bp[col]; v1 += g_bp[col+1]; }
                *(__nv_bfloat162*)&out[row*F + col] = __floats2bfloat162_rn(v0, v1);
            }
        }
    }
}

// ---------------- G2D: g2 tiles (blocks 0..255) + diag rows (blocks 256..4351)
// g2: M'_T[g][k] = sum_n up[n,g]*beta[n,k]; 64x64 tiles, warp tile 32x32.
// diag: d[i] = alpha_i . beta_i (one warp per row, 4 rows per 128-thr block).
__global__ __launch_bounds__(128) void g2d() {
    const int tid = threadIdx.x, lane = tid & 31, wid = tid >> 5;

    if (blockIdx.x >= 256) {
        // ---- diag part ----
        int j = blockIdx.x - 256;                 // 0..4095
        int gw = j*4 + wid;                        // row 0..16383
        const __nv_bfloat162* a = (const __nv_bfloat162*)(g_alpha + gw*F);
        const __nv_bfloat162* b = (const __nv_bfloat162*)(g_beta  + gw*F);
        float s = 0.f;
        #pragma unroll
        for (int t = lane; t < 128; t += 32) {
            float2 av = __bfloat1622float2(a[t]);
            float2 bv = __bfloat1622float2(b[t]);
            s = fmaf(av.x, bv.x, s);
            s = fmaf(av.y, bv.y, s);
        }
        #pragma unroll
        for (int o = 16; o > 0; o >>= 1) s += __shfl_xor_sync(0xffffffffu, s, o);
        if (lane == 0) g_d[gw] = s;
        return;
    }

    // ---- g2 part ----
    const int b  = blockIdx.x >> 4;               // 0..15
    const int m0 = (blockIdx.x & 3) * 64;         // g
    const int n0 = ((blockIdx.x >> 2) & 3) * 64;  // k
    const __nv_bfloat16* __restrict__ Aop = g_up   + b*NTOK*F;
    const __nv_bfloat16* __restrict__ Bop = g_beta + b*NTOK*F;

    __shared__ __nv_bfloat16 Ut[2][32][72];
    __shared__ __nv_bfloat16 Bt[2][32][72];

    const int wm = wid & 1, wn = wid >> 1;

    float acc[2][4][4];
    #pragma unroll
    for (int i = 0; i < 2; ++i)
        #pragma unroll
        for (int j = 0; j < 4; ++j)
            #pragma unroll
            for (int e = 0; e < 4; ++e) acc[i][j][e] = 0.f;

#define G2_LOAD(buf, rt) { \
    _Pragma("unroll") \
    for (int l = 0; l < 2; ++l) { \
        int id = tid + l*128; \
        int r = id >> 3, c8 = (id & 7)*8; \
        cp16(&Ut[buf][r][c8], &Aop[((rt) + r)*F + m0 + c8]); \
        cp16(&Bt[buf][r][c8], &Bop[((rt) + r)*F + n0 + c8]); \
    } cp_commit(); }

    G2_LOAD(0, 0)
    const int NIT = NTOK/32;
    for (int it = 0; it < NIT; ++it) {
        if (it + 1 < NIT) { G2_LOAD((it+1)&1, (it+1)*32) cp_wait1(); }
        else cp_wait0();
        __syncthreads();
        const int buf = it & 1;
        #pragma unroll
        for (int ks = 0; ks < 2; ++ks) {
            const int r0 = ks * 16;
            uint32_t a[2][4];
            #pragma unroll
            for (int mt = 0; mt < 2; ++mt) {
                int rr = r0 + (lane & 7) + ((lane >> 4) & 1)*8;
                int cm = wm*32 + mt*16 + ((lane >> 3) & 1)*8;
                ldmx4t(a[mt], cvta_s(&Ut[buf][rr][cm]));
            }
            uint32_t bfr[4][2];
            {
                uint32_t t[4];
                int rr = r0 + (lane & 7) + ((lane >> 3) & 1)*8;
                #pragma unroll
                for (int bt = 0; bt < 2; ++bt) {
                    int cn = wn*32 + bt*16 + ((lane >> 4) & 1)*8;
                    ldmx4t(t, cvta_s(&Bt[buf][rr][cn]));
                    bfr[bt*2][0] = t[0]; bfr[bt*2][1] = t[1];
                    bfr[bt*2+1][0] = t[2]; bfr[bt*2+1][1] = t[3];
                }
            }
            #pragma unroll
            for (int mt = 0; mt < 2; ++mt)
                #pragma unroll
                for (int nt = 0; nt < 4; ++nt)
                    mma_bf16(acc[mt][nt], a[mt], bfr[nt]);
        }
        __syncthreads();
    }
#undef G2_LOAD

    const int rc = lane >> 2, cc = (lane & 3)*2;
    __nv_bfloat16* __restrict__ Mp = g_Mp + b*F*F;
    #pragma unroll
    for (int mt = 0; mt < 2; ++mt) {
        int rb = m0 + wm*32 + mt*16 + rc;
        #pragma unroll
        for (int nt = 0; nt < 4; ++nt) {
            int col = n0 + wn*32 + nt*8 + cc;
            #pragma unroll
            for (int h = 0; h < 2; ++h) {
                int row = rb + h*8;
                *(__nv_bfloat162*)&Mp[row*F + col] =
                    __floats2bfloat162_rn(acc[mt][nt][2*h], acc[mt][nt][2*h+1]);
            }
        }
    }
}

// ---------------- G3: out = (alpha @ M'_T^T - d*up)/N + x --------------------
__global__ __launch_bounds__(256, 2) void g3_out(const float* __restrict__ x,
                                                 float* __restrict__ out) {
    extern __shared__ char smem_raw[];
    const int row0 = blockIdx.x * 128;
    const int col0 = blockIdx.y * 128;
    const int b = row0 >> 10;
    const __nv_bfloat16* __restrict__ Mp = g_Mp + b*F*F;   // [g][k] K-major
    const __nv_bfloat16* aG = g_alpha + row0*F;
    const __nv_bfloat16* bG = Mp + col0*F;

    GEMM_CORE(aG, bG, F)

    const float inv = 1.0f / (float)NTOK;
    const int rc = lane >> 2, cc = (lane & 3)*2;
    #pragma unroll
    for (int mt = 0; mt < 2; ++mt) {
        int rb = row0 + wm*32 + mt*16 + rc;
        #pragma unroll
        for (int h = 0; h < 2; ++h) {
            int row = rb + h*8;
            float di = g_d[row];
            #pragma unroll
            for (int nt = 0; nt < 8; ++nt) {
                int col = col0 + wn*64 + nt*8 + cc;
                float2 uv = __bfloat1622float2(*(const __nv_bfloat162*)&g_up[row*F + col]);
                float2 xv = *(const float2*)&x[row*F + col];
                float2 o;
                o.x = (acc[mt][nt][2*h]   - di*uv.x) * inv + xv.x;
                o.y = (acc[mt][nt][2*h+1] - di*uv.y) * inv + xv.y;
                *(float2*)&out[row*F + col] = o;
            }
        }
    }
}

// ---------------------------------------------------------------------------
extern "C" void kernel_launch(void* const* d_in, const int* in_sizes, int n_in,
                              void* d_out, int out_size) {
    const float* x  = (const float*)d_in[0];
    const float* Wa = (const float*)d_in[1];
    const float* Wb = (const float*)d_in[2];
    const float* Wu = (const float*)d_in[3];
    const float* bu = (const float*)d_in[4];
    const float* Wr = (const float*)d_in[5];
    float* out = (float*)d_out;

    static int inited = 0;
    static cudaStream_t s2;
    static cudaEvent_t eA, eB;
    if (!inited) {
        cudaFuncSetAttribute(g1_proj, cudaFuncAttributeMaxDynamicSharedMemorySize, GEMM_SMEM);
        cudaFuncSetAttribute(g3_out, cudaFuncAttributeMaxDynamicSharedMemorySize, GEMM_SMEM);
        cudaStreamCreateWithFlags(&s2, cudaStreamNonBlocking);
        cudaEventCreateWithFlags(&eA, cudaEventDisableTiming);
        cudaEventCreateWithFlags(&eB, cudaEventDisableTiming);
        inited = 1;
    }

    // fork: kconv_x on s2 || kprep_w on main
    cudaEventRecord(eA, 0);
    cudaStreamWaitEvent(s2, eA, 0);
    kconv_x<<<ROWS*F/4/256, 256, 0, s2>>>(x);
    kprep_w<<<F, F>>>(Wr, Wu, bu, Wa, Wb);
    cudaEventRecord(eB, s2);
    cudaStreamWaitEvent(0, eB, 0);

    g1_proj<<<dim3(ROWS/128, F/128, 3), 256, GEMM_SMEM>>>();
    g2d<<<256 + ROWS/4, 128>>>();
    g3_out<<<dim3(ROWS/128, F/128), 256, GEMM_SMEM>>>(x, out);
}

// round 12
// speedup vs baseline: 1.0892x; 1.0276x over previous
#include <cuda_runtime.h>
#include <cuda_bf16.h>
#include <cstdint>

#define F 256
#define NTOK 1024
#define NB 16
#define ROWS (NB*NTOK)   // 16384

// ---------------- scratch ----------------------------------------------------
__device__ __nv_bfloat16 g_xb[ROWS*F];
__device__ __nv_bfloat16 g_alpha[ROWS*F];
__device__ __nv_bfloat16 g_beta[ROWS*F];
__device__ __nv_bfloat16 g_up[ROWS*F];
__device__ __nv_bfloat16 g_Mp[NB*F*F];       // M'_T[b][g][k]  (K-major)
__device__ __nv_bfloat16 g_Wbf[3*F*F];
__device__ float g_bp[F];
__device__ float g_d[ROWS];

// ---------------- helpers ----------------------------------------------------
__device__ __forceinline__ uint32_t cvta_s(const void* p) {
    return (uint32_t)__cvta_generic_to_shared(p);
}
__device__ __forceinline__ void cp16(void* s, const void* g) {
    asm volatile("cp.async.cg.shared.global [%0], [%1], 16;\n"
        :: "r"(cvta_s(s)), "l"(g));
}
__device__ __forceinline__ void cp_commit() { asm volatile("cp.async.commit_group;\n"); }
__device__ __forceinline__ void cp_wait1()  { asm volatile("cp.async.wait_group 1;\n"); }
__device__ __forceinline__ void cp_wait0()  { asm volatile("cp.async.wait_group 0;\n"); }

__device__ __forceinline__ void ldmx4(uint32_t r[4], uint32_t addr) {
    asm volatile("ldmatrix.sync.aligned.m8n8.x4.shared.b16 {%0,%1,%2,%3}, [%4];\n"
        : "=r"(r[0]), "=r"(r[1]), "=r"(r[2]), "=r"(r[3]) : "r"(addr));
}
__device__ __forceinline__ void ldmx4t(uint32_t r[4], uint32_t addr) {
    asm volatile("ldmatrix.sync.aligned.m8n8.x4.trans.shared.b16 {%0,%1,%2,%3}, [%4];\n"
        : "=r"(r[0]), "=r"(r[1]), "=r"(r[2]), "=r"(r[3]) : "r"(addr));
}
__device__ __forceinline__ void mma_bf16(float c[4], const uint32_t a[4], const uint32_t b[2]) {
    asm volatile(
        "mma.sync.aligned.m16n8k16.row.col.f32.bf16.bf16.f32 "
        "{%0,%1,%2,%3}, {%4,%5,%6,%7}, {%8,%9}, {%0,%1,%2,%3};\n"
        : "+f"(c[0]), "+f"(c[1]), "+f"(c[2]), "+f"(c[3])
        : "r"(a[0]), "r"(a[1]), "r"(a[2]), "r"(a[3]), "r"(b[0]), "r"(b[1]));
}

// ---------------- KPREP_W: combined weight + all weight conversions ----------
__global__ void kprep_w(const float* __restrict__ Wr,
                        const float* __restrict__ Wu,
                        const float* __restrict__ bu,
                        const float* __restrict__ Wa,
                        const float* __restrict__ Wb) {
    __shared__ float sWr[F];
    int g = blockIdx.x;
    int f = threadIdx.x;
    sWr[f] = Wr[g*F + f];
    __syncthreads();
    float acc = 0.f;
    #pragma unroll 8
    for (int h = 0; h < F; ++h) acc = fmaf(sWr[h], Wu[h*F + f], acc);
    g_Wbf[2*F*F + g*F + f] = __float2bfloat16(acc);
    g_Wbf[0*F*F + g*F + f] = __float2bfloat16(Wa[g*F + f]);
    g_Wbf[1*F*F + g*F + f] = __float2bfloat16(Wb[g*F + f]);
    if (f == 0) {
        float bb = 0.f;
        for (int h = 0; h < F; ++h) bb = fmaf(sWr[h], bu[h], bb);
        g_bp[g] = bb;
    }
}

// ---------------- kconv_x ----------------------------------------------------
__global__ void kconv_x(const float* __restrict__ x) {
    int i = blockIdx.x * blockDim.x + threadIdx.x;
    float4 v = ((const float4*)x)[i];
    ((__nv_bfloat162*)g_xb)[2*i]   = __floats2bfloat162_rn(v.x, v.y);
    ((__nv_bfloat162*)g_xb)[2*i+1] = __floats2bfloat162_rn(v.z, v.w);
}

// ============================================================================
// GEMM core (R6/R9-proven): CTA 128x128, BK=64, 8 warps (4m x 2n),
// warp tile 32x64. Smem + register-fragment double buffering.
// ============================================================================
#define LDSTRIDE 72

#define LOAD_FRAGS(dst_a, dst_b, buf, k0) { \
    _Pragma("unroll") \
    for (int mt = 0; mt < 2; ++mt) \
        ldmx4(dst_a[mt], cvta_s(&As[((buf)*128 + wm*32 + mt*16 + (lane & 15))*LDSTRIDE \
                                    + (k0) + (lane >> 4)*8])); \
    _Pragma("unroll") \
    for (int bt = 0; bt < 4; ++bt) { \
        uint32_t t[4]; \
        int n  = wn*64 + bt*16 + (lane & 7) + ((lane >> 4) & 1)*8; \
        int kk = (k0) + ((lane >> 3) & 1)*8; \
        ldmx4(t, cvta_s(&Bs[((buf)*128 + n)*LDSTRIDE + kk])); \
        dst_b[bt*2][0] = t[0]; dst_b[bt*2][1] = t[1]; \
        dst_b[bt*2+1][0] = t[2]; dst_b[bt*2+1][1] = t[3]; \
    } }

#define GEMM_CORE(aG, bG, NK) \
    __nv_bfloat16* As = (__nv_bfloat16*)smem_raw; \
    __nv_bfloat16* Bs = As + 2*128*LDSTRIDE; \
    const int tid = threadIdx.x, lane = tid & 31, wid = tid >> 5; \
    const int wm = wid & 3, wn = wid >> 2; \
    float acc[2][8][4]; \
    _Pragma("unroll") \
    for (int i = 0; i < 2; ++i) \
        _Pragma("unroll") \
        for (int j = 0; j < 8; ++j) \
            _Pragma("unroll") \
            for (int e = 0; e < 4; ++e) acc[i][j][e] = 0.f; \
    { \
        int r = tid >> 3, c8 = (tid & 7)*8; \
        _Pragma("unroll") \
        for (int l = 0; l < 4; ++l) { \
            cp16(&As[(0*128 + r + l*32)*LDSTRIDE + c8], &(aG)[(r + l*32)*F + c8]); \
            cp16(&Bs[(0*128 + r + l*32)*LDSTRIDE + c8], &(bG)[(r + l*32)*F + c8]); \
        } \
        cp_commit(); \
    } \
    const int NIT = (NK)/64; \
    for (int it = 0; it < NIT; ++it) { \
        if (it + 1 < NIT) { \
            int kt = (it+1)*64, buf = (it+1)&1; \
            int r = tid >> 3, c8 = (tid & 7)*8; \
            _Pragma("unroll") \
            for (int l = 0; l < 4; ++l) { \
                cp16(&As[(buf*128 + r + l*32)*LDSTRIDE + c8], &(aG)[(r + l*32)*F + kt + c8]); \
                cp16(&Bs[(buf*128 + r + l*32)*LDSTRIDE + c8], &(bG)[(r + l*32)*F + kt + c8]); \
            } \
            cp_commit(); cp_wait1(); \
        } else cp_wait0(); \
        __syncthreads(); \
        const int buf = it & 1; \
        uint32_t afr[2][2][4]; \
        uint32_t bfr[2][8][2]; \
        LOAD_FRAGS(afr[0], bfr[0], buf, 0) \
        _Pragma("unroll") \
        for (int ks = 0; ks < 4; ++ks) { \
            const int cur = ks & 1, nxt = cur ^ 1; \
            if (ks < 3) LOAD_FRAGS(afr[nxt], bfr[nxt], buf, (ks+1)*16) \
            _Pragma("unroll") \
            for (int mt = 0; mt < 2; ++mt) \
                _Pragma("unroll") \
                for (int nt = 0; nt < 8; ++nt) \
                    mma_bf16(acc[mt][nt], afr[cur][mt], bfr[cur][nt]); \
        } \
        __syncthreads(); \
    }

#define GEMM_SMEM (2*128*LDSTRIDE*2*2)   // 73728 B

// ---------------- G1: projections (z = blockIdx.z + zbase) -------------------
__global__ __launch_bounds__(256, 2) void g1_proj(int zbase) {
    extern __shared__ char smem_raw[];
    const int z = blockIdx.z + zbase;
    const int row0 = blockIdx.x * 128;
    const int col0 = blockIdx.y * 128;
    const __nv_bfloat16* __restrict__ W = g_Wbf + z*F*F;
    __nv_bfloat16* __restrict__ out = (z == 0) ? g_alpha : (z == 1) ? g_beta : g_up;
    const __nv_bfloat16* aG = g_xb + row0*F;
    const __nv_bfloat16* bG = W + col0*F;

    GEMM_CORE(aG, bG, F)

    const int rc = lane >> 2, cc = (lane & 3)*2;
    #pragma unroll
    for (int mt = 0; mt < 2; ++mt) {
        int rb = row0 + wm*32 + mt*16 + rc;
        #pragma unroll
        for (int nt = 0; nt < 8; ++nt) {
            int col = col0 + wn*64 + nt*8 + cc;
            #pragma unroll
            for (int h = 0; h < 2; ++h) {
                int row = rb + h*8;
                float v0 = acc[mt][nt][2*h], v1 = acc[mt][nt][2*h+1];
                if (z == 2) { v0 += g_bp[col]; v1 += g_bp[col+1]; }
                *(__nv_bfloat162*)&out[row*F + col] = __floats2bfloat162_rn(v0, v1);
            }
        }
    }
}

// ---------------- kdiag ------------------------------------------------------
__global__ void kdiag() {
    int gw = (blockIdx.x * blockDim.x + threadIdx.x) >> 5;
    int lane = threadIdx.x & 31;
    const __nv_bfloat162* a = (const __nv_bfloat162*)(g_alpha + gw*F);
    const __nv_bfloat162* b = (const __nv_bfloat162*)(g_beta  + gw*F);
    float s = 0.f;
    #pragma unroll
    for (int t = lane; t < 128; t += 32) {
        float2 av = __bfloat1622float2(a[t]);
        float2 bv = __bfloat1622float2(b[t]);
        s = fmaf(av.x, bv.x, s);
        s = fmaf(av.y, bv.y, s);
    }
    #pragma unroll
    for (int o = 16; o > 0; o >>= 1) s += __shfl_xor_sync(0xffffffffu, s, o);
    if (lane == 0) g_d[gw] = s;
}

// ---------------- G2: M'_T[g][k] = sum_n up[n,g]*beta[n,k] -------------------
// 64x64 tiles, grid (4,4,16) = 256 CTAs, 128 threads, warp tile 32x32, BK=32.
__global__ __launch_bounds__(128) void g2_mprime() {
    const int b  = blockIdx.z;
    const int m0 = blockIdx.x * 64;        // g
    const int n0 = blockIdx.y * 64;        // k
    const __nv_bfloat16* __restrict__ Aop = g_up   + b*NTOK*F;
    const __nv_bfloat16* __restrict__ Bop = g_beta + b*NTOK*F;

    __shared__ __nv_bfloat16 Ut[2][32][72];
    __shared__ __nv_bfloat16 Bt[2][32][72];

    const int tid = threadIdx.x, lane = tid & 31, wid = tid >> 5;
    const int wm = wid & 1, wn = wid >> 1;

    float acc[2][4][4];
    #pragma unroll
    for (int i = 0; i < 2; ++i)
        #pragma unroll
        for (int j = 0; j < 4; ++j)
            #pragma unroll
            for (int e = 0; e < 4; ++e) acc[i][j][e] = 0.f;

#define G2_LOAD(buf, rt) { \
    _Pragma("unroll") \
    for (int l = 0; l < 2; ++l) { \
        int id = tid + l*128; \
        int r = id >> 3, c8 = (id & 7)*8; \
        cp16(&Ut[buf][r][c8], &Aop[((rt) + r)*F + m0 + c8]); \
        cp16(&Bt[buf][r][c8], &Bop[((rt) + r)*F + n0 + c8]); \
    } cp_commit(); }

    G2_LOAD(0, 0)
    const int NIT = NTOK/32;
    for (int it = 0; it < NIT; ++it) {
        if (it + 1 < NIT) { G2_LOAD((it+1)&1, (it+1)*32) cp_wait1(); }
        else cp_wait0();
        __syncthreads();
        const int buf = it & 1;
        #pragma unroll
        for (int ks = 0; ks < 2; ++ks) {
            const int r0 = ks * 16;
            uint32_t a[2][4];
            #pragma unroll
            for (int mt = 0; mt < 2; ++mt) {
                int rr = r0 + (lane & 7) + ((lane >> 4) & 1)*8;
                int cm = wm*32 + mt*16 + ((lane >> 3) & 1)*8;
                ldmx4t(a[mt], cvta_s(&Ut[buf][rr][cm]));
            }
            uint32_t bfr[4][2];
            {
                uint32_t t[4];
                int rr = r0 + (lane & 7) + ((lane >> 3) & 1)*8;
                #pragma unroll
                for (int bt = 0; bt < 2; ++bt) {
                    int cn = wn*32 + bt*16 + ((lane >> 4) & 1)*8;
                    ldmx4t(t, cvta_s(&Bt[buf][rr][cn]));
                    bfr[bt*2][0] = t[0]; bfr[bt*2][1] = t[1];
                    bfr[bt*2+1][0] = t[2]; bfr[bt*2+1][1] = t[3];
                }
            }
            #pragma unroll
            for (int mt = 0; mt < 2; ++mt)
                #pragma unroll
                for (int nt = 0; nt < 4; ++nt)
                    mma_bf16(acc[mt][nt], a[mt], bfr[nt]);
        }
        __syncthreads();
    }
#undef G2_LOAD

    const int rc = lane >> 2, cc = (lane & 3)*2;
    __nv_bfloat16* __restrict__ Mp = g_Mp + b*F*F;
    #pragma unroll
    for (int mt = 0; mt < 2; ++mt) {
        int rb = m0 + wm*32 + mt*16 + rc;
        #pragma unroll
        for (int nt = 0; nt < 4; ++nt) {
            int col = n0 + wn*32 + nt*8 + cc;
            #pragma unroll
            for (int h = 0; h < 2; ++h) {
                int row = rb + h*8;
                *(__nv_bfloat162*)&Mp[row*F + col] =
                    __floats2bfloat162_rn(acc[mt][nt][2*h], acc[mt][nt][2*h+1]);
            }
        }
    }
}

// ---------------- G3: out = (alpha @ M'_T^T - d*up)/N + x --------------------
__global__ __launch_bounds__(256, 2) void g3_out(const float* __restrict__ x,
                                                 float* __restrict__ out) {
    extern __shared__ char smem_raw[];
    const int row0 = blockIdx.x * 128;
    const int col0 = blockIdx.y * 128;
    const int b = row0 >> 10;
    const __nv_bfloat16* __restrict__ Mp = g_Mp + b*F*F;   // [g][k] K-major
    const __nv_bfloat16* aG = g_alpha + row0*F;
    const __nv_bfloat16* bG = Mp + col0*F;

    GEMM_CORE(aG, bG, F)

    const float inv = 1.0f / (float)NTOK;
    const int rc = lane >> 2, cc = (lane & 3)*2;
    #pragma unroll
    for (int mt = 0; mt < 2; ++mt) {
        int rb = row0 + wm*32 + mt*16 + rc;
        #pragma unroll
        for (int h = 0; h < 2; ++h) {
            int row = rb + h*8;
            float di = g_d[row];
            #pragma unroll
            for (int nt = 0; nt < 8; ++nt) {
                int col = col0 + wn*64 + nt*8 + cc;
                float2 uv = __bfloat1622float2(*(const __nv_bfloat162*)&g_up[row*F + col]);
                float2 xv = *(const float2*)&x[row*F + col];
                float2 o;
                o.x = (acc[mt][nt][2*h]   - di*uv.x) * inv + xv.x;
                o.y = (acc[mt][nt][2*h+1] - di*uv.y) * inv + xv.y;
                *(float2*)&out[row*F + col] = o;
            }
        }
    }
}

// ---------------------------------------------------------------------------
extern "C" void kernel_launch(void* const* d_in, const int* in_sizes, int n_in,
                              void* d_out, int out_size) {
    const float* x  = (const float*)d_in[0];
    const float* Wa = (const float*)d_in[1];
    const float* Wb = (const float*)d_in[2];
    const float* Wu = (const float*)d_in[3];
    const float* bu = (const float*)d_in[4];
    const float* Wr = (const float*)d_in[5];
    float* out = (float*)d_out;

    static int inited = 0;
    static cudaStream_t s2;
    static cudaEvent_t eA, eB, eC, eD;
    if (!inited) {
        cudaFuncSetAttribute(g1_proj, cudaFuncAttributeMaxDynamicSharedMemorySize, GEMM_SMEM);
        cudaFuncSetAttribute(g3_out, cudaFuncAttributeMaxDynamicSharedMemorySize, GEMM_SMEM);
        cudaStreamCreateWithFlags(&s2, cudaStreamNonBlocking);
        cudaEventCreateWithFlags(&eA, cudaEventDisableTiming);
        cudaEventCreateWithFlags(&eB, cudaEventDisableTiming);
        cudaEventCreateWithFlags(&eC, cudaEventDisableTiming);
        cudaEventCreateWithFlags(&eD, cudaEventDisableTiming);
        inited = 1;
    }

    // fork: kconv_x on s2 || kprep_w on main
    cudaEventRecord(eA, 0);
    cudaStreamWaitEvent(s2, eA, 0);
    kconv_x<<<ROWS*F/4/256, 256, 0, s2>>>(x);
    kprep_w<<<F, F>>>(Wr, Wu, bu, Wa, Wb);
    cudaEventRecord(eB, s2);
    cudaStreamWaitEvent(0, eB, 0);

    // beta + up on main first (g2's inputs)
    g1_proj<<<dim3(ROWS/128, F/128, 2), 256, GEMM_SMEM>>>(1);

    // fork: alpha + kdiag on s2 || g2 on main
    cudaEventRecord(eC, 0);
    cudaStreamWaitEvent(s2, eC, 0);
    g1_proj<<<dim3(ROWS/128, F/128, 1), 256, GEMM_SMEM, s2>>>(0);
    kdiag<<<ROWS*32/256, 256, 0, s2>>>();
    g2_mprime<<<dim3(F/64, F/64, NB), 128>>>();
    cudaEventRecord(eD, s2);
    cudaStreamWaitEvent(0, eD, 0);

    g3_out<<<dim3(ROWS/128, F/128), 256, GEMM_SMEM>>>(x, out);
}

// round 13
// speedup vs baseline: 1.1542x; 1.0597x over previous
#include <cuda_runtime.h>
#include <cuda_bf16.h>
#include <cstdint>

#define F 256
#define NTOK 1024
#define NB 16
#define ROWS (NB*NTOK)   // 16384

// ---------------- scratch ----------------------------------------------------
__device__ __nv_bfloat16 g_xb[ROWS*F];
__device__ __nv_bfloat16 g_alpha[ROWS*F];
__device__ __nv_bfloat16 g_beta[ROWS*F];
__device__ __nv_bfloat16 g_up[ROWS*F];
__device__ __nv_bfloat16 g_Mp[NB*F*F];       // M'_T[b][g][k]  (K-major)
__device__ __nv_bfloat16 g_Wbf[3*F*F];
__device__ float g_bp[F];
__device__ float g_d[ROWS];

// ---------------- helpers ----------------------------------------------------
__device__ __forceinline__ uint32_t cvta_s(const void* p) {
    return (uint32_t)__cvta_generic_to_shared(p);
}
__device__ __forceinline__ void cp16(void* s, const void* g) {
    asm volatile("cp.async.cg.shared.global [%0], [%1], 16;\n"
        :: "r"(cvta_s(s)), "l"(g));
}
__device__ __forceinline__ void cp_commit() { asm volatile("cp.async.commit_group;\n"); }
__device__ __forceinline__ void cp_wait1()  { asm volatile("cp.async.wait_group 1;\n"); }
__device__ __forceinline__ void cp_wait0()  { asm volatile("cp.async.wait_group 0;\n"); }

__device__ __forceinline__ void ldmx4(uint32_t r[4], uint32_t addr) {
    asm volatile("ldmatrix.sync.aligned.m8n8.x4.shared.b16 {%0,%1,%2,%3}, [%4];\n"
        : "=r"(r[0]), "=r"(r[1]), "=r"(r[2]), "=r"(r[3]) : "r"(addr));
}
__device__ __forceinline__ void ldmx4t(uint32_t r[4], uint32_t addr) {
    asm volatile("ldmatrix.sync.aligned.m8n8.x4.trans.shared.b16 {%0,%1,%2,%3}, [%4];\n"
        : "=r"(r[0]), "=r"(r[1]), "=r"(r[2]), "=r"(r[3]) : "r"(addr));
}
__device__ __forceinline__ void mma_bf16(float c[4], const uint32_t a[4], const uint32_t b[2]) {
    asm volatile(
        "mma.sync.aligned.m16n8k16.row.col.f32.bf16.bf16.f32 "
        "{%0,%1,%2,%3}, {%4,%5,%6,%7}, {%8,%9}, {%0,%1,%2,%3};\n"
        : "+f"(c[0]), "+f"(c[1]), "+f"(c[2]), "+f"(c[3])
        : "r"(a[0]), "r"(a[1]), "r"(a[2]), "r"(a[3]), "r"(b[0]), "r"(b[1]));
}

// ---------------- KPREP_W: combined weight + all weight conversions ----------
__global__ void kprep_w(const float* __restrict__ Wr,
                        const float* __restrict__ Wu,
                        const float* __restrict__ bu,
                        const float* __restrict__ Wa,
                        const float* __restrict__ Wb) {
    __shared__ float sWr[F];
    int g = blockIdx.x;
    int f = threadIdx.x;
    sWr[f] = Wr[g*F + f];
    __syncthreads();
    float acc = 0.f;
    #pragma unroll 8
    for (int h = 0; h < F; ++h) acc = fmaf(sWr[h], Wu[h*F + f], acc);
    g_Wbf[2*F*F + g*F + f] = __float2bfloat16(acc);
    g_Wbf[0*F*F + g*F + f] = __float2bfloat16(Wa[g*F + f]);
    g_Wbf[1*F*F + g*F + f] = __float2bfloat16(Wb[g*F + f]);
    if (f == 0) {
        float bb = 0.f;
        for (int h = 0; h < F; ++h) bb = fmaf(sWr[h], bu[h], bb);
        g_bp[g] = bb;
    }
}

// ---------------- kconv_x ----------------------------------------------------
__global__ void kconv_x(const float* __restrict__ x) {
    int i = blockIdx.x * blockDim.x + threadIdx.x;
    float4 v = ((const float4*)x)[i];
    ((__nv_bfloat162*)g_xb)[2*i]   = __floats2bfloat162_rn(v.x, v.y);
    ((__nv_bfloat162*)g_xb)[2*i+1] = __floats2bfloat162_rn(v.z, v.w);
}

// ============================================================================
// GEMM core (R6/R9-proven): CTA 128x128, BK=64, 8 warps (4m x 2n),
// warp tile 32x64. Smem + register-fragment double buffering.
// ============================================================================
#define LDSTRIDE 72

#define LOAD_FRAGS(dst_a, dst_b, buf, k0) { \
    _Pragma("unroll") \
    for (int mt = 0; mt < 2; ++mt) \
        ldmx4(dst_a[mt], cvta_s(&As[((buf)*128 + wm*32 + mt*16 + (lane & 15))*LDSTRIDE \
                                    + (k0) + (lane >> 4)*8])); \
    _Pragma("unroll") \
    for (int bt = 0; bt < 4; ++bt) { \
        uint32_t t[4]; \
        int n  = wn*64 + bt*16 + (lane & 7) + ((lane >> 4) & 1)*8; \
        int kk = (k0) + ((lane >> 3) & 1)*8; \
        ldmx4(t, cvta_s(&Bs[((buf)*128 + n)*LDSTRIDE + kk])); \
        dst_b[bt*2][0] = t[0]; dst_b[bt*2][1] = t[1]; \
        dst_b[bt*2+1][0] = t[2]; dst_b[bt*2+1][1] = t[3]; \
    } }

#define GEMM_CORE(aG, bG, NK) \
    __nv_bfloat16* As = (__nv_bfloat16*)smem_raw; \
    __nv_bfloat16* Bs = As + 2*128*LDSTRIDE; \
    const int tid = threadIdx.x, lane = tid & 31, wid = tid >> 5; \
    const int wm = wid & 3, wn = wid >> 2; \
    float acc[2][8][4]; \
    _Pragma("unroll") \
    for (int i = 0; i < 2; ++i) \
        _Pragma("unroll") \
        for (int j = 0; j < 8; ++j) \
            _Pragma("unroll") \
            for (int e = 0; e < 4; ++e) acc[i][j][e] = 0.f; \
    { \
        int r = tid >> 3, c8 = (tid & 7)*8; \
        _Pragma("unroll") \
        for (int l = 0; l < 4; ++l) { \
            cp16(&As[(0*128 + r + l*32)*LDSTRIDE + c8], &(aG)[(r + l*32)*F + c8]); \
            cp16(&Bs[(0*128 + r + l*32)*LDSTRIDE + c8], &(bG)[(r + l*32)*F + c8]); \
        } \
        cp_commit(); \
    } \
    const int NIT = (NK)/64; \
    for (int it = 0; it < NIT; ++it) { \
        if (it + 1 < NIT) { \
            int kt = (it+1)*64, buf = (it+1)&1; \
            int r = tid >> 3, c8 = (tid & 7)*8; \
            _Pragma("unroll") \
            for (int l = 0; l < 4; ++l) { \
                cp16(&As[(buf*128 + r + l*32)*LDSTRIDE + c8], &(aG)[(r + l*32)*F + kt + c8]); \
                cp16(&Bs[(buf*128 + r + l*32)*LDSTRIDE + c8], &(bG)[(r + l*32)*F + kt + c8]); \
            } \
            cp_commit(); cp_wait1(); \
        } else cp_wait0(); \
        __syncthreads(); \
        const int buf = it & 1; \
        uint32_t afr[2][2][4]; \
        uint32_t bfr[2][8][2]; \
        LOAD_FRAGS(afr[0], bfr[0], buf, 0) \
        _Pragma("unroll") \
        for (int ks = 0; ks < 4; ++ks) { \
            const int cur = ks & 1, nxt = cur ^ 1; \
            if (ks < 3) LOAD_FRAGS(afr[nxt], bfr[nxt], buf, (ks+1)*16) \
            _Pragma("unroll") \
            for (int mt = 0; mt < 2; ++mt) \
                _Pragma("unroll") \
                for (int nt = 0; nt < 8; ++nt) \
                    mma_bf16(acc[mt][nt], afr[cur][mt], bfr[cur][nt]); \
        } \
        __syncthreads(); \
    }

#define GEMM_SMEM (2*128*LDSTRIDE*2*2)   // 73728 B

// ---------------- G1: projections (3 z-planes in one launch) -----------------
__global__ __launch_bounds__(256, 2) void g1_proj() {
    extern __shared__ char smem_raw[];
    const int z = blockIdx.z;
    const int row0 = blockIdx.x * 128;
    const int col0 = blockIdx.y * 128;
    const __nv_bfloat16* __restrict__ W = g_Wbf + z*F*F;
    __nv_bfloat16* __restrict__ out = (z == 0) ? g_alpha : (z == 1) ? g_beta : g_up;
    const __nv_bfloat16* aG = g_xb + row0*F;
    const __nv_bfloat16* bG = W + col0*F;

    GEMM_CORE(aG, bG, F)

    const int rc = lane >> 2, cc = (lane & 3)*2;
    #pragma unroll
    for (int mt = 0; mt < 2; ++mt) {
        int rb = row0 + wm*32 + mt*16 + rc;
        #pragma unroll
        for (int nt = 0; nt < 8; ++nt) {
            int col = col0 + wn*64 + nt*8 + cc;
            #pragma unroll
            for (int h = 0; h < 2; ++h) {
                int row = rb + h*8;
                float v0 = acc[mt][nt][2*h], v1 = acc[mt][nt][2*h+1];
                if (z == 2) { v0 += g_bp[col]; v1 += g_bp[col+1]; }
                *(__nv_bfloat162*)&out[row*F + col] = __floats2bfloat162_rn(v0, v1);
            }
        }
    }
}

// ---------------- kdiag ------------------------------------------------------
__global__ void kdiag() {
    int gw = (blockIdx.x * blockDim.x + threadIdx.x) >> 5;
    int lane = threadIdx.x & 31;
    const __nv_bfloat162* a = (const __nv_bfloat162*)(g_alpha + gw*F);
    const __nv_bfloat162* b = (const __nv_bfloat162*)(g_beta  + gw*F);
    float s = 0.f;
    #pragma unroll
    for (int t = lane; t < 128; t += 32) {
        float2 av = __bfloat1622float2(a[t]);
        float2 bv = __bfloat1622float2(b[t]);
        s = fmaf(av.x, bv.x, s);
        s = fmaf(av.y, bv.y, s);
    }
    #pragma unroll
    for (int o = 16; o > 0; o >>= 1) s += __shfl_xor_sync(0xffffffffu, s, o);
    if (lane == 0) g_d[gw] = s;
}

// ---------------- G2: M'_T[g][k] = sum_n up[n,g]*beta[n,k] -------------------
// 64x64 tiles, grid (4,4,16) = 256 CTAs, 128 threads, warp tile 32x32, BK=32.
__global__ __launch_bounds__(128) void g2_mprime() {
    const int b  = blockIdx.z;
    const int m0 = blockIdx.x * 64;        // g
    const int n0 = blockIdx.y * 64;        // k
    const __nv_bfloat16* __restrict__ Aop = g_up   + b*NTOK*F;
    const __nv_bfloat16* __restrict__ Bop = g_beta + b*NTOK*F;

    __shared__ __nv_bfloat16 Ut[2][32][72];
    __shared__ __nv_bfloat16 Bt[2][32][72];

    const int tid = threadIdx.x, lane = tid & 31, wid = tid >> 5;
    const int wm = wid & 1, wn = wid >> 1;

    float acc[2][4][4];
    #pragma unroll
    for (int i = 0; i < 2; ++i)
        #pragma unroll
        for (int j = 0; j < 4; ++j)
            #pragma unroll
            for (int e = 0; e < 4; ++e) acc[i][j][e] = 0.f;

#define G2_LOAD(buf, rt) { \
    _Pragma("unroll") \
    for (int l = 0; l < 2; ++l) { \
        int id = tid + l*128; \
        int r = id >> 3, c8 = (id & 7)*8; \
        cp16(&Ut[buf][r][c8], &Aop[((rt) + r)*F + m0 + c8]); \
        cp16(&Bt[buf][r][c8], &Bop[((rt) + r)*F + n0 + c8]); \
    } cp_commit(); }

    G2_LOAD(0, 0)
    const int NIT = NTOK/32;
    for (int it = 0; it < NIT; ++it) {
        if (it + 1 < NIT) { G2_LOAD((it+1)&1, (it+1)*32) cp_wait1(); }
        else cp_wait0();
        __syncthreads();
        const int buf = it & 1;
        #pragma unroll
        for (int ks = 0; ks < 2; ++ks) {
            const int r0 = ks * 16;
            uint32_t a[2][4];
            #pragma unroll
            for (int mt = 0; mt < 2; ++mt) {
                int rr = r0 + (lane & 7) + ((lane >> 4) & 1)*8;
                int cm = wm*32 + mt*16 + ((lane >> 3) & 1)*8;
                ldmx4t(a[mt], cvta_s(&Ut[buf][rr][cm]));
            }
            uint32_t bfr[4][2];
            {
                uint32_t t[4];
                int rr = r0 + (lane & 7) + ((lane >> 3) & 1)*8;
                #pragma unroll
                for (int bt = 0; bt < 2; ++bt) {
                    int cn = wn*32 + bt*16 + ((lane >> 4) & 1)*8;
                    ldmx4t(t, cvta_s(&Bt[buf][rr][cn]));
                    bfr[bt*2][0] = t[0]; bfr[bt*2][1] = t[1];
                    bfr[bt*2+1][0] = t[2]; bfr[bt*2+1][1] = t[3];
                }
            }
            #pragma unroll
            for (int mt = 0; mt < 2; ++mt)
                #pragma unroll
                for (int nt = 0; nt < 4; ++nt)
                    mma_bf16(acc[mt][nt], a[mt], bfr[nt]);
        }
        __syncthreads();
    }
#undef G2_LOAD

    const int rc = lane >> 2, cc = (lane & 3)*2;
    __nv_bfloat16* __restrict__ Mp = g_Mp + b*F*F;
    #pragma unroll
    for (int mt = 0; mt < 2; ++mt) {
        int rb = m0 + wm*32 + mt*16 + rc;
        #pragma unroll
        for (int nt = 0; nt < 4; ++nt) {
            int col = n0 + wn*32 + nt*8 + cc;
            #pragma unroll
            for (int h = 0; h < 2; ++h) {
                int row = rb + h*8;
                *(__nv_bfloat162*)&Mp[row*F + col] =
                    __floats2bfloat162_rn(acc[mt][nt][2*h], acc[mt][nt][2*h+1]);
            }
        }
    }
}

// ---------------- G3: out = (alpha @ M'_T^T - d*up)/N + x --------------------
__global__ __launch_bounds__(256, 2) void g3_out(const float* __restrict__ x,
                                                 float* __restrict__ out) {
    extern __shared__ char smem_raw[];
    const int row0 = blockIdx.x * 128;
    const int col0 = blockIdx.y * 128;
    const int b = row0 >> 10;
    const __nv_bfloat16* __restrict__ Mp = g_Mp + b*F*F;   // [g][k] K-major
    const __nv_bfloat16* aG = g_alpha + row0*F;
    const __nv_bfloat16* bG = Mp + col0*F;

    GEMM_CORE(aG, bG, F)

    const float inv = 1.0f / (float)NTOK;
    const int rc = lane >> 2, cc = (lane & 3)*2;
    #pragma unroll
    for (int mt = 0; mt < 2; ++mt) {
        int rb = row0 + wm*32 + mt*16 + rc;
        #pragma unroll
        for (int h = 0; h < 2; ++h) {
            int row = rb + h*8;
            float di = g_d[row];
            #pragma unroll
            for (int nt = 0; nt < 8; ++nt) {
                int col = col0 + wn*64 + nt*8 + cc;
                float2 uv = __bfloat1622float2(*(const __nv_bfloat162*)&g_up[row*F + col]);
                float2 xv = *(const float2*)&x[row*F + col];
                float2 o;
                o.x = (acc[mt][nt][2*h]   - di*uv.x) * inv + xv.x;
                o.y = (acc[mt][nt][2*h+1] - di*uv.y) * inv + xv.y;
                *(float2*)&out[row*F + col] = o;
            }
        }
    }
}

// ---------------------------------------------------------------------------
extern "C" void kernel_launch(void* const* d_in, const int* in_sizes, int n_in,
                              void* d_out, int out_size) {
    const float* x  = (const float*)d_in[0];
    const float* Wa = (const float*)d_in[1];
    const float* Wb = (const float*)d_in[2];
    const float* Wu = (const float*)d_in[3];
    const float* bu = (const float*)d_in[4];
    const float* Wr = (const float*)d_in[5];
    float* out = (float*)d_out;

    static int inited = 0;
    static cudaStream_t s2;
    static cudaEvent_t eA, eB, eC, eD;
    if (!inited) {
        cudaFuncSetAttribute(g1_proj, cudaFuncAttributeMaxDynamicSharedMemorySize, GEMM_SMEM);
        cudaFuncSetAttribute(g3_out, cudaFuncAttributeMaxDynamicSharedMemorySize, GEMM_SMEM);
        cudaStreamCreateWithFlags(&s2, cudaStreamNonBlocking);
        cudaEventCreateWithFlags(&eA, cudaEventDisableTiming);
        cudaEventCreateWithFlags(&eB, cudaEventDisableTiming);
        cudaEventCreateWithFlags(&eC, cudaEventDisableTiming);
        cudaEventCreateWithFlags(&eD, cudaEventDisableTiming);
        inited = 1;
    }

    // fork: kconv_x on s2 || kprep_w on main
    cudaEventRecord(eA, 0);
    cudaStreamWaitEvent(s2, eA, 0);
    kconv_x<<<ROWS*F/4/256, 256, 0, s2>>>(x);
    kprep_w<<<F, F>>>(Wr, Wu, bu, Wa, Wb);
    cudaEventRecord(eB, s2);
    cudaStreamWaitEvent(0, eB, 0);

    g1_proj<<<dim3(ROWS/128, F/128, 3), 256, GEMM_SMEM>>>();

    // fork: kdiag on s2 || g2 on main
    cudaEventRecord(eC, 0);
    cudaStreamWaitEvent(s2, eC, 0);
    kdiag<<<ROWS*32/256, 256, 0, s2>>>();
    g2_mprime<<<dim3(F/64, F/64, NB), 128>>>();
    cudaEventRecord(eD, s2);
    cudaStreamWaitEvent(0, eD, 0);

    g3_out<<<dim3(ROWS/128, F/128), 256, GEMM_SMEM>>>(x, out);
}